// round 7
// baseline (speedup 1.0000x reference)
#include <cuda_runtime.h>
#include <cuda_bf16.h>
#include <math.h>

#define H        128
#define SB       136      // bf16 row stride: lane i -> banks 4i..4i+3, conflict-free LDS.128
#define STRIDE   132      // fp32 partials padding
#define NCTA     128
#define NTHREADS 512
#define MAXIT    500
#define TOLF     1e-3f

__device__ float g_res[MAXIT];   // per-iteration residual accumulators
__device__ int   g_cnt[MAXIT];   // per-iteration post counters (skew-safe)

struct __align__(16) Smem {
    __nv_bfloat16 Wy0b[H * SB];   // row-major bf16
    __nv_bfloat16 Wy1b[H * SB];
    __nv_bfloat16 W1pb[H * SB];
    __nv_bfloat16 Wy0t[H * SB];   // transposed bf16 (for column passes)
    __nv_bfloat16 Wy1t[H * SB];
    __nv_bfloat16 W1pt[H * SB];
    float yv0[2][H];
    float yv1[2][H];
    float zz [2][H];
    float v2 [2][H];
    float v1 [2][H];
    float P1[4][2][STRIDE];   // [quarter][sample][h]
    float P2[4][2][STRIDE];
    float xbuf[2][H];
    float ubuf[2][H];
    float red[8];
    int   flag;
};

__global__ void pblnn_init_kernel() {
    int t = blockIdx.x * blockDim.x + threadIdx.x;
    if (t < MAXIT) { g_res[t] = 0.f; g_cnt[t] = 0; }
}

__device__ __forceinline__ float softplus_f(float s) {
    float e = __expf(s);
    float z = __logf(1.f + e);
    return (s > 15.f) ? s : z;
}

__device__ __forceinline__ void spsig(float s, float& z, float& sg) {
    float e = __expf(s);
    float zz_ = __logf(1.f + e);
    float sgg = e / (1.f + e);
    if (s > 15.f) { zz_ = s; sgg = 1.f; }
    z = zz_; sg = sgg;
}

// one-time single-sample dot: smem fp32 vector . gmem fp32 row
__device__ __forceinline__ float dot1(const float* xs, const float* __restrict__ w) {
    float a = 0.f, b = 0.f;
#pragma unroll
    for (int j = 0; j < H; j += 8) {
        float4 wv0 = __ldg((const float4*)&w[j]);
        float4 wv1 = __ldg((const float4*)&w[j + 4]);
        float4 u0 = *(const float4*)&xs[j];
        float4 u1 = *(const float4*)&xs[j + 4];
        a += wv0.x * u0.x + wv0.y * u0.y + wv0.z * u0.z + wv0.w * u0.w;
        b += wv1.x * u1.x + wv1.y * u1.y + wv1.z * u1.z + wv1.w * u1.w;
    }
    return a + b;
}

__device__ __forceinline__ void store4bf(__nv_bfloat16* p, float4 v) {
    *(__nv_bfloat162*)(p)     = __floats2bfloat162_rn(v.x, v.y);
    *(__nv_bfloat162*)(p + 2) = __floats2bfloat162_rn(v.z, v.w);
}

// dual-sample partial dot over 32 k: bf16 weight row segment x fp32 smem vectors
__device__ __forceinline__ void bfdot(const __nv_bfloat16* Wrow,
                                      const float* v0, const float* v1,
                                      float& m0, float& m1) {
#pragma unroll
    for (int c = 0; c < 4; c++) {
        uint4 wr = *(const uint4*)(Wrow + 8 * c);
        float2 w0 = __bfloat1622float2(*(const __nv_bfloat162*)&wr.x);
        float2 w1 = __bfloat1622float2(*(const __nv_bfloat162*)&wr.y);
        float2 w2 = __bfloat1622float2(*(const __nv_bfloat162*)&wr.z);
        float2 w3 = __bfloat1622float2(*(const __nv_bfloat162*)&wr.w);
        float4 a0 = *(const float4*)&v0[8 * c];
        float4 a1 = *(const float4*)&v0[8 * c + 4];
        float4 b0 = *(const float4*)&v1[8 * c];
        float4 b1 = *(const float4*)&v1[8 * c + 4];
        m0 += w0.x * a0.x + w0.y * a0.y + w1.x * a0.z + w1.y * a0.w
            + w2.x * a1.x + w2.y * a1.y + w3.x * a1.z + w3.y * a1.w;
        m1 += w0.x * b0.x + w0.y * b0.y + w1.x * b0.z + w1.y * b0.w
            + w2.x * b1.x + w2.y * b1.y + w3.x * b1.z + w3.y * b1.w;
    }
}

__global__ __launch_bounds__(NTHREADS, 1)
void pblnn_kernel(
    const float* __restrict__ x,      const float* __restrict__ y,
    const float* __restrict__ wuu0_w, const float* __restrict__ wuu0_b,
    const float* __restrict__ wyu0_w, const float* __restrict__ wyu0_b,
    const float* __restrict__ wy0,
    const float* __restrict__ wu0_w,  const float* __restrict__ wu0_b,
    const float* __restrict__ wuu1_w, const float* __restrict__ wuu1_b,
    const float* __restrict__ wzu1_w, const float* __restrict__ wzu1_b,
    const float* __restrict__ wz1,
    const float* __restrict__ wyu1_w, const float* __restrict__ wyu1_b,
    const float* __restrict__ wy1,
    const float* __restrict__ wu1_w,  const float* __restrict__ wu1_b,
    const float* __restrict__ wzu2_w, const float* __restrict__ wzu2_b,
    const float* __restrict__ wz2,
    const float* __restrict__ wyu2_w, const float* __restrict__ wyu2_b,
    const float* __restrict__ wy2,
    float* __restrict__ out)
{
    extern __shared__ char smem_raw[];
    Smem& S = *reinterpret_cast<Smem*>(smem_raw);

    const int tid  = threadIdx.x;
    const int h    = tid & (H - 1);
    const int q    = tid >> 7;          // quarter 0..3
    const int k0   = q * 32;
    const bool act = (q < 2);           // elementwise lanes; s = q
    const int s    = q & 1;
    const int samp = blockIdx.x * 2;

    // ---- stage x + bf16 weights (normal) into smem ----
    for (int e = tid; e < 2 * H; e += NTHREADS)
        S.xbuf[e >> 7][e & 127] = x[samp * H + e];
    for (int e = tid; e < H * H / 4; e += NTHREADS) {
        int r = e >> 5, c4 = (e & 31) * 4;
        store4bf(&S.Wy0b[r * SB + c4], __ldg((const float4*)&wy0[r * H + c4]));
        store4bf(&S.Wy1b[r * SB + c4], __ldg((const float4*)&wy1[r * H + c4]));
        float4 wv = __ldg((const float4*)&wz1[r * H + c4]);
        wv.x = fmaxf(wv.x, 0.f); wv.y = fmaxf(wv.y, 0.f);
        wv.z = fmaxf(wv.z, 0.f); wv.w = fmaxf(wv.w, 0.f);
        store4bf(&S.W1pb[r * SB + c4], wv);
    }
    // ---- transposed bf16 copies (WT[c][r] = W[r][c]) ----
    for (int e = tid; e < H * H / 4; e += NTHREADS) {
        int c = e >> 5, r4 = (e & 31) * 4;
        float4 v;
        v.x = __ldg(&wy0[(r4 + 0) * H + c]); v.y = __ldg(&wy0[(r4 + 1) * H + c]);
        v.z = __ldg(&wy0[(r4 + 2) * H + c]); v.w = __ldg(&wy0[(r4 + 3) * H + c]);
        store4bf(&S.Wy0t[c * SB + r4], v);
        v.x = __ldg(&wy1[(r4 + 0) * H + c]); v.y = __ldg(&wy1[(r4 + 1) * H + c]);
        v.z = __ldg(&wy1[(r4 + 2) * H + c]); v.w = __ldg(&wy1[(r4 + 3) * H + c]);
        store4bf(&S.Wy1t[c * SB + r4], v);
        v.x = fmaxf(__ldg(&wz1[(r4 + 0) * H + c]), 0.f);
        v.y = fmaxf(__ldg(&wz1[(r4 + 1) * H + c]), 0.f);
        v.z = fmaxf(__ldg(&wz1[(r4 + 2) * H + c]), 0.f);
        v.w = fmaxf(__ldg(&wz1[(r4 + 3) * H + c]), 0.f);
        store4bf(&S.W1pt[c * SB + r4], v);
    }
    __syncthreads();

    // ---- y-independent precompute (fp32, one-time) ----
    float a0r = 0.f, a1r = 0.f, c0r = 0.f, c1r = 0.f, zur = 0.f;
    float vw2 = 0.f, a2w = 0.f, yr = 0.f;
    float y1r = 1.f, yhist = 1.f;
    float zs1r = 0.f, gAr = 0.f;

    if (act) {
        const float* xs = S.xbuf[s];
        float u0 = softplus_f(dot1(xs, &wuu0_w[h * H]) + wuu0_b[h]);
        a0r = dot1(xs, &wyu0_w[h * H]) + wyu0_b[h];
        c0r = dot1(xs, &wu0_w[h * H]) + wu0_b[h];
        S.ubuf[s][h] = u0;
    }
    __syncthreads();
    float u1 = 0.f;
    if (act) {
        const float* us = S.ubuf[s];
        u1  = softplus_f(dot1(us, &wuu1_w[h * H]) + wuu1_b[h]);
        zur = softplus_f(dot1(us, &wzu1_w[h * H]) + wzu1_b[h]);
        a1r = dot1(us, &wyu1_w[h * H]) + wyu1_b[h];
        c1r = dot1(us, &wu1_w[h * H]) + wu1_b[h];
    }
    __syncthreads();
    if (act) S.ubuf[s][h] = u1;
    __syncthreads();
    if (act) {
        const float* us = S.ubuf[s];
        a2w = (dot1(us, &wyu2_w[h * H]) + wyu2_b[h]) * wy2[h];
        float zu2 = softplus_f(dot1(us, wzu2_w) + wzu2_b[0]);
        vw2 = zu2 * fmaxf(wz2[h], 0.f);
        yr = y[(samp + s) * H + h];
        S.yv0[s][h] = a0r;      // y1 = 1
        S.yv1[s][h] = a1r;
    }
    __syncthreads();            // yv ready for iter 0

    // ---- fixed-point iterations: lag-2 convergence pipeline ----
    int broke = 0;
    for (int it = 0; it < MAXIT; ++it) {
        if (tid == 0 && it > 0) {
            float n0 = sqrtf(S.red[0] + S.red[1] + S.red[2] + S.red[3]);
            float n1 = sqrtf(S.red[4] + S.red[5] + S.red[6] + S.red[7]);
            atomicAdd(&g_res[it - 1], n0 + n1);
            __threadfence();
            atomicAdd(&g_cnt[it - 1], 1);
        }
        if (tid == 384) {
            int f = 0;
            if (it >= 2) {
                int k = it - 2;
                while (*((volatile int*)&g_cnt[k]) < NCTA) { }
                __threadfence();
                if (*((volatile float*)&g_res[k]) * (1.f / 256.f) < TOLF) f = 1;
            }
            S.flag = f;
        }

        // M1: s1 partial = Wy0[h][k0..k0+32) . yv0
        {
            float m0 = 0.f, m1 = 0.f;
            bfdot(&S.Wy0b[h * SB + k0], &S.yv0[0][k0], &S.yv0[1][k0], m0, m1);
            S.P1[q][0][h] = m0;  S.P1[q][1][h] = m1;
        }
        __syncthreads();                                   // #2

        if (act) {
            float s1 = S.P1[0][s][h] + S.P1[1][s][h] + S.P1[2][s][h] + S.P1[3][s][h] + c0r;
            float z1, sg1;
            spsig(s1, z1, sg1);
            zs1r = sg1 * zur;
            S.zz[s][h] = z1 * zur;
        }
        __syncthreads();                                   // #3

        // M2: s2 partial = W1p@zz + Wy1@yv1
        {
            float m0 = 0.f, m1 = 0.f;
            bfdot(&S.W1pb[h * SB + k0], &S.zz[0][k0], &S.zz[1][k0], m0, m1);
            bfdot(&S.Wy1b[h * SB + k0], &S.yv1[0][k0], &S.yv1[1][k0], m0, m1);
            S.P1[q][0][h] = m0;  S.P1[q][1][h] = m1;
        }
        __syncthreads();                                   // #4

        if (act) {
            float s2 = S.P1[0][s][h] + S.P1[1][s][h] + S.P1[2][s][h] + S.P1[3][s][h] + c1r;
            float sg2 = 1.f / (1.f + __expf(-s2));
            S.v2[s][h] = vw2 * sg2;
        }
        __syncthreads();                                   // #5

        // C: tv = W1p^T @ v2, gA = Wy1^T @ v2 via transposed copies (row streaming)
        {
            float t0 = 0.f, t1 = 0.f, g0 = 0.f, g1 = 0.f;
            bfdot(&S.W1pt[h * SB + k0], &S.v2[0][k0], &S.v2[1][k0], t0, t1);
            bfdot(&S.Wy1t[h * SB + k0], &S.v2[0][k0], &S.v2[1][k0], g0, g1);
            S.P1[q][0][h] = t0;  S.P1[q][1][h] = t1;
            S.P2[q][0][h] = g0;  S.P2[q][1][h] = g1;
        }
        __syncthreads();                                   // #6

        if (act) {
            float tv = S.P1[0][s][h] + S.P1[1][s][h] + S.P1[2][s][h] + S.P1[3][s][h];
            gAr      = S.P2[0][s][h] + S.P2[1][s][h] + S.P2[2][s][h] + S.P2[3][s][h];
            S.v1[s][h] = tv * zs1r;
        }
        __syncthreads();                                   // #7

        // D: gB = Wy0^T @ v1 via transposed copy
        {
            float g0 = 0.f, g1 = 0.f;
            bfdot(&S.Wy0t[h * SB + k0], &S.v1[0][k0], &S.v1[1][k0], g0, g1);
            S.P1[q][0][h] = g0;  S.P1[q][1][h] = g1;
        }
        __syncthreads();                                   // #8

        float rres = 0.f;
        if (act) {
            float gB = S.P1[0][s][h] + S.P1[1][s][h] + S.P1[2][s][h] + S.P1[3][s][h];
            float g = a1r * gAr + a0r * gB + a2w + 0.5f * y1r;
            rres = yr - g;
            float qq = rres * rres;
#pragma unroll
            for (int o = 16; o; o >>= 1)
                qq += __shfl_xor_sync(0xffffffffu, qq, o);
            if ((h & 31) == 0) S.red[tid >> 5] = qq;   // warps 0..7
        }

        // flag = conv(it-2); break BEFORE this iteration's update.
        if (S.flag) { broke = 1; break; }

        if (act) {
            yhist = y1r;                       // y1_after(it-1)
            y1r += (4.f / (float)(it + 1)) * rres;
            S.yv0[s][h] = y1r * a0r;
            S.yv1[s][h] = y1r * a1r;
        }
        __syncthreads();     // #E
    }
    if (broke && act) y1r = yhist;   // exact revert to y1_after(break_it - 2)

    // ---- output: mean over dims of (y1 + y) per sample ----
    float o = act ? (y1r + yr) : 0.f;
    if (act) {
#pragma unroll
        for (int off = 16; off; off >>= 1)
            o += __shfl_xor_sync(0xffffffffu, o, off);
        if ((h & 31) == 0) S.red[tid >> 5] = o;
    }
    __syncthreads();
    if (tid == 0) {
        out[samp]     = (S.red[0] + S.red[1] + S.red[2] + S.red[3]) * (1.f / 128.f);
        out[samp + 1] = (S.red[4] + S.red[5] + S.red[6] + S.red[7]) * (1.f / 128.f);
    }
}

extern "C" void kernel_launch(void* const* d_in, const int* in_sizes, int n_in,
                              void* d_out, int out_size) {
    (void)in_sizes; (void)n_in; (void)out_size;
    const float* x      = (const float*)d_in[0];
    const float* y      = (const float*)d_in[1];
    const float* wuu0_w = (const float*)d_in[2];
    const float* wuu0_b = (const float*)d_in[3];
    const float* wyu0_w = (const float*)d_in[4];
    const float* wyu0_b = (const float*)d_in[5];
    const float* wy0    = (const float*)d_in[6];
    const float* wu0_w  = (const float*)d_in[7];
    const float* wu0_b  = (const float*)d_in[8];
    const float* wuu1_w = (const float*)d_in[9];
    const float* wuu1_b = (const float*)d_in[10];
    const float* wzu1_w = (const float*)d_in[11];
    const float* wzu1_b = (const float*)d_in[12];
    const float* wz1    = (const float*)d_in[13];
    const float* wyu1_w = (const float*)d_in[14];
    const float* wyu1_b = (const float*)d_in[15];
    const float* wy1    = (const float*)d_in[16];
    const float* wu1_w  = (const float*)d_in[17];
    const float* wu1_b  = (const float*)d_in[18];
    const float* wzu2_w = (const float*)d_in[19];
    const float* wzu2_b = (const float*)d_in[20];
    const float* wz2    = (const float*)d_in[21];
    const float* wyu2_w = (const float*)d_in[22];
    const float* wyu2_b = (const float*)d_in[23];
    const float* wy2    = (const float*)d_in[24];
    // d_in[25] (wu2_w), d_in[26] (wu2_b) do not affect the gradient / output.

    size_t smem = sizeof(Smem);
    cudaFuncSetAttribute(pblnn_kernel, cudaFuncAttributeMaxDynamicSharedMemorySize, (int)smem);

    pblnn_init_kernel<<<2, 256>>>();
    pblnn_kernel<<<NCTA, NTHREADS, smem>>>(
        x, y,
        wuu0_w, wuu0_b, wyu0_w, wyu0_b, wy0, wu0_w, wu0_b,
        wuu1_w, wuu1_b, wzu1_w, wzu1_b, wz1, wyu1_w, wyu1_b, wy1, wu1_w, wu1_b,
        wzu2_w, wzu2_b, wz2, wyu2_w, wyu2_b, wy2,
        (float*)d_out);
}

// round 8
// speedup vs baseline: 1.7289x; 1.7289x over previous
#include <cuda_runtime.h>
#include <math.h>

#define H        128
#define STRIDE   132      // 132 % 32 == 4 -> conflict-free row AND column smem access
#define NCTA     128
#define NTHREADS 512
#define MAXIT    500
#define TOLF     1e-3f

// per-(iteration, CTA) residual slots; -1 = not yet posted, >=0 = posted value.
__device__ float g_part[MAXIT * NCTA];

struct __align__(16) Smem {
    float Wy0[H * STRIDE];
    float Wy1[H * STRIDE];
    float W1p[H * STRIDE];
    float yv0[2][H];
    float yv1[2][H];
    float zz [2][H];
    float v2 [2][H];
    float v1 [2][H];
    float P1[4][2][STRIDE];   // [quarter][sample][h]
    float P2[4][2][STRIDE];
    float xbuf[2][H];
    float ubuf0[2][H];
    float ubuf1[2][H];
    float red[8];
    int   flag;
};

__global__ void pblnn_init_kernel() {
    int t = blockIdx.x * blockDim.x + threadIdx.x;
    if (t < MAXIT * NCTA) g_part[t] = -1.f;
}

__device__ __forceinline__ float softplus_f(float s) {
    float e = __expf(s);
    float z = __logf(1.f + e);
    return (s > 15.f) ? s : z;
}

__device__ __forceinline__ void spsig(float s, float& z, float& sg) {
    float e = __expf(s);
    float zz_ = __logf(1.f + e);
    float sgg = e / (1.f + e);
    if (s > 15.f) { zz_ = s; sgg = 1.f; }
    z = zz_; sg = sgg;
}

// one-time single-sample dot: smem fp32 vector . gmem fp32 row (full 128)
__device__ __forceinline__ float dot1(const float* xs, const float* __restrict__ w) {
    float a = 0.f, b = 0.f;
#pragma unroll
    for (int j = 0; j < H; j += 8) {
        float4 wv0 = __ldg((const float4*)&w[j]);
        float4 wv1 = __ldg((const float4*)&w[j + 4]);
        float4 u0 = *(const float4*)&xs[j];
        float4 u1 = *(const float4*)&xs[j + 4];
        a += wv0.x * u0.x + wv0.y * u0.y + wv0.z * u0.z + wv0.w * u0.w;
        b += wv1.x * u1.x + wv1.y * u1.y + wv1.z * u1.z + wv1.w * u1.w;
    }
    return a + b;
}

// quarter dot (32 wide) for both samples: gmem weight row segment x smem vectors
__device__ __forceinline__ void qdot2(const float* __restrict__ wseg,
                                      const float* v0, const float* v1,
                                      float& p0, float& p1) {
    float a0 = 0.f, b0 = 0.f, a1 = 0.f, b1 = 0.f;
#pragma unroll
    for (int c = 0; c < 8; c += 2) {
        float4 w  = __ldg((const float4*)&wseg[4 * c]);
        float4 w2 = __ldg((const float4*)&wseg[4 * c + 4]);
        float4 x0  = *(const float4*)&v0[4 * c];
        float4 x02 = *(const float4*)&v0[4 * c + 4];
        float4 x1  = *(const float4*)&v1[4 * c];
        float4 x12 = *(const float4*)&v1[4 * c + 4];
        a0 += w.x * x0.x + w.y * x0.y + w.z * x0.z + w.w * x0.w;
        b0 += w2.x * x02.x + w2.y * x02.y + w2.z * x02.z + w2.w * x02.w;
        a1 += w.x * x1.x + w.y * x1.y + w.z * x1.z + w.w * x1.w;
        b1 += w2.x * x12.x + w2.y * x12.y + w2.z * x12.z + w2.w * x12.w;
    }
    p0 = a0 + b0; p1 = a1 + b1;
}

__global__ __launch_bounds__(NTHREADS, 1)
void pblnn_kernel(
    const float* __restrict__ x,      const float* __restrict__ y,
    const float* __restrict__ wuu0_w, const float* __restrict__ wuu0_b,
    const float* __restrict__ wyu0_w, const float* __restrict__ wyu0_b,
    const float* __restrict__ wy0,
    const float* __restrict__ wu0_w,  const float* __restrict__ wu0_b,
    const float* __restrict__ wuu1_w, const float* __restrict__ wuu1_b,
    const float* __restrict__ wzu1_w, const float* __restrict__ wzu1_b,
    const float* __restrict__ wz1,
    const float* __restrict__ wyu1_w, const float* __restrict__ wyu1_b,
    const float* __restrict__ wy1,
    const float* __restrict__ wu1_w,  const float* __restrict__ wu1_b,
    const float* __restrict__ wzu2_w, const float* __restrict__ wzu2_b,
    const float* __restrict__ wz2,
    const float* __restrict__ wyu2_w, const float* __restrict__ wyu2_b,
    const float* __restrict__ wy2,
    float* __restrict__ out)
{
    extern __shared__ char smem_raw[];
    Smem& S = *reinterpret_cast<Smem*>(smem_raw);

    const int tid  = threadIdx.x;
    const int lane = tid & 31;
    const int wrp  = tid >> 5;
    const int h    = tid & (H - 1);
    const int q    = tid >> 7;          // quarter 0..3
    const int k0   = q * 32;
    const bool act = (q < 2);           // elementwise lanes; s = q
    const int s    = q & 1;
    const int samp = blockIdx.x * 2;

    // ---- stage weights into smem (float4, stride-132 padded) + x ----
    for (int e = tid; e < H * H / 4; e += NTHREADS) {
        int r = e >> 5, c4 = (e & 31) * 4;
        *(float4*)&S.Wy0[r * STRIDE + c4] = __ldg((const float4*)&wy0[r * H + c4]);
        *(float4*)&S.Wy1[r * STRIDE + c4] = __ldg((const float4*)&wy1[r * H + c4]);
        float4 wv = __ldg((const float4*)&wz1[r * H + c4]);
        wv.x = fmaxf(wv.x, 0.f); wv.y = fmaxf(wv.y, 0.f);
        wv.z = fmaxf(wv.z, 0.f); wv.w = fmaxf(wv.w, 0.f);
        *(float4*)&S.W1p[r * STRIDE + c4] = wv;
    }
    for (int e = tid; e < 2 * H; e += NTHREADS)
        S.xbuf[e >> 7][e & 127] = x[samp * H + e];
    __syncthreads();

    // ---- y-independent precompute, parallelized via quarter dots ----
    float a0r = 0.f, a1r = 0.f, c0r = 0.f, c1r = 0.f, zur = 0.f;
    float vw2 = 0.f, a2w = 0.f, yr = 0.f;
    float y1r = 1.f, yhist = 1.f;
    float zs1r = 0.f, gAr = 0.f;

    // R1: wuu0 @ x -> u0 ; wyu0 @ x -> a0
    {
        float p0, p1, r0, r1;
        qdot2(&wuu0_w[h * H + k0], &S.xbuf[0][k0], &S.xbuf[1][k0], p0, p1);
        qdot2(&wyu0_w[h * H + k0], &S.xbuf[0][k0], &S.xbuf[1][k0], r0, r1);
        S.P1[q][0][h] = p0;  S.P1[q][1][h] = p1;
        S.P2[q][0][h] = r0;  S.P2[q][1][h] = r1;
    }
    __syncthreads();
    if (act) {
        float su = S.P1[0][s][h] + S.P1[1][s][h] + S.P1[2][s][h] + S.P1[3][s][h];
        S.ubuf0[s][h] = softplus_f(su + wuu0_b[h]);
        a0r = S.P2[0][s][h] + S.P2[1][s][h] + S.P2[2][s][h] + S.P2[3][s][h] + wyu0_b[h];
    }
    __syncthreads();
    // R2: wu0 @ x -> c0 ; wuu1 @ u0 -> u1
    {
        float p0, p1, r0, r1;
        qdot2(&wu0_w[h * H + k0], &S.xbuf[0][k0], &S.xbuf[1][k0], p0, p1);
        qdot2(&wuu1_w[h * H + k0], &S.ubuf0[0][k0], &S.ubuf0[1][k0], r0, r1);
        S.P1[q][0][h] = p0;  S.P1[q][1][h] = p1;
        S.P2[q][0][h] = r0;  S.P2[q][1][h] = r1;
    }
    __syncthreads();
    if (act) {
        c0r = S.P1[0][s][h] + S.P1[1][s][h] + S.P1[2][s][h] + S.P1[3][s][h] + wu0_b[h];
        float su = S.P2[0][s][h] + S.P2[1][s][h] + S.P2[2][s][h] + S.P2[3][s][h];
        S.ubuf1[s][h] = softplus_f(su + wuu1_b[h]);
    }
    __syncthreads();
    // R3: wzu1 @ u0 -> zu ; wyu1 @ u0 -> a1
    {
        float p0, p1, r0, r1;
        qdot2(&wzu1_w[h * H + k0], &S.ubuf0[0][k0], &S.ubuf0[1][k0], p0, p1);
        qdot2(&wyu1_w[h * H + k0], &S.ubuf0[0][k0], &S.ubuf0[1][k0], r0, r1);
        S.P1[q][0][h] = p0;  S.P1[q][1][h] = p1;
        S.P2[q][0][h] = r0;  S.P2[q][1][h] = r1;
    }
    __syncthreads();
    if (act) {
        float su = S.P1[0][s][h] + S.P1[1][s][h] + S.P1[2][s][h] + S.P1[3][s][h];
        zur = softplus_f(su + wzu1_b[h]);
        a1r = S.P2[0][s][h] + S.P2[1][s][h] + S.P2[2][s][h] + S.P2[3][s][h] + wyu1_b[h];
    }
    __syncthreads();
    // R4: wu1 @ u0 -> c1 ; wyu2 @ u1 -> a2
    {
        float p0, p1, r0, r1;
        qdot2(&wu1_w[h * H + k0], &S.ubuf0[0][k0], &S.ubuf0[1][k0], p0, p1);
        qdot2(&wyu2_w[h * H + k0], &S.ubuf1[0][k0], &S.ubuf1[1][k0], r0, r1);
        S.P1[q][0][h] = p0;  S.P1[q][1][h] = p1;
        S.P2[q][0][h] = r0;  S.P2[q][1][h] = r1;
    }
    __syncthreads();
    if (act) {
        c1r = S.P1[0][s][h] + S.P1[1][s][h] + S.P1[2][s][h] + S.P1[3][s][h] + wu1_b[h];
        float su = S.P2[0][s][h] + S.P2[1][s][h] + S.P2[2][s][h] + S.P2[3][s][h];
        a2w = (su + wyu2_b[h]) * wy2[h];
        // R5: single-row zu2 = sp(wzu2 . u1 + b)
        float zu2 = softplus_f(dot1(S.ubuf1[s], wzu2_w) + wzu2_b[0]);
        vw2 = zu2 * fmaxf(wz2[h], 0.f);
        yr = y[(samp + s) * H + h];
        S.yv0[s][h] = a0r;      // y1 = 1
        S.yv1[s][h] = a1r;
    }
    __syncthreads();            // yv ready for iter 0

    // ---- fixed-point iterations: lag-2, atomic-free convergence pipeline ----
    int broke = 0;
    for (int it = 0; it < MAXIT; ++it) {
        // post residual of it-1: one plain volatile store, value doubles as flag
        if (tid == 416 && it > 0) {
            float n0 = sqrtf(S.red[0] + S.red[1] + S.red[2] + S.red[3]);
            float n1 = sqrtf(S.red[4] + S.red[5] + S.red[6] + S.red[7]);
            *((volatile float*)&g_part[(it - 1) * NCTA + blockIdx.x]) = n0 + n1;
        }
        // checker warp: cooperative poll + sum of lag-2 slots (overlaps M1)
        if (wrp == 12) {
            int f = 0;
            if (it >= 2) {
                volatile const float* gp = &g_part[(it - 2) * NCTA];
                float sum;
                for (;;) {
                    float v0 = gp[lane], v1 = gp[lane + 32];
                    float v2 = gp[lane + 64], v3 = gp[lane + 96];
                    bool ok = (v0 >= 0.f) & (v1 >= 0.f) & (v2 >= 0.f) & (v3 >= 0.f);
                    if (__all_sync(0xffffffffu, ok)) { sum = v0 + v1 + v2 + v3; break; }
                }
#pragma unroll
                for (int o = 16; o; o >>= 1)
                    sum += __shfl_xor_sync(0xffffffffu, sum, o);
                if (sum * (1.f / 256.f) < TOLF) f = 1;
            }
            if (lane == 0) S.flag = f;
        }

        // M1: s1 partial = Wy0[h][k0..k0+32) . yv0
        {
            const float4* W  = (const float4*)&S.Wy0[h * STRIDE + k0];
            const float4* V0 = (const float4*)&S.yv0[0][k0];
            const float4* V1 = (const float4*)&S.yv0[1][k0];
            float m0a = 0.f, m0b = 0.f, m1a = 0.f, m1b = 0.f;
#pragma unroll
            for (int c = 0; c < 8; c += 2) {
                float4 w = W[c], a = V0[c], b = V1[c];
                m0a += w.x * a.x + w.y * a.y + w.z * a.z + w.w * a.w;
                m1a += w.x * b.x + w.y * b.y + w.z * b.z + w.w * b.w;
                float4 w2 = W[c + 1], a2 = V0[c + 1], b2 = V1[c + 1];
                m0b += w2.x * a2.x + w2.y * a2.y + w2.z * a2.z + w2.w * a2.w;
                m1b += w2.x * b2.x + w2.y * b2.y + w2.z * b2.z + w2.w * b2.w;
            }
            S.P1[q][0][h] = m0a + m0b;  S.P1[q][1][h] = m1a + m1b;
        }
        __syncthreads();                                   // #2

        if (act) {
            float s1 = S.P1[0][s][h] + S.P1[1][s][h] + S.P1[2][s][h] + S.P1[3][s][h] + c0r;
            float z1, sg1;
            spsig(s1, z1, sg1);
            zs1r = sg1 * zur;
            S.zz[s][h] = z1 * zur;
        }
        __syncthreads();                                   // #3

        // M2: s2 partial = W1p@zz + Wy1@yv1
        {
            const float4* WA = (const float4*)&S.W1p[h * STRIDE + k0];
            const float4* WB = (const float4*)&S.Wy1[h * STRIDE + k0];
            const float4* Z0 = (const float4*)&S.zz[0][k0];
            const float4* Z1 = (const float4*)&S.zz[1][k0];
            const float4* Y0 = (const float4*)&S.yv1[0][k0];
            const float4* Y1 = (const float4*)&S.yv1[1][k0];
            float mA0 = 0.f, mA1 = 0.f, mB0 = 0.f, mB1 = 0.f;
#pragma unroll
            for (int c = 0; c < 8; c++) {
                float4 A = WA[c], Bm = WB[c];
                float4 z0 = Z0[c], z1v = Z1[c], u0v = Y0[c], u1v = Y1[c];
                mA0 += A.x * z0.x + A.y * z0.y + A.z * z0.z + A.w * z0.w;
                mB0 += Bm.x * u0v.x + Bm.y * u0v.y + Bm.z * u0v.z + Bm.w * u0v.w;
                mA1 += A.x * z1v.x + A.y * z1v.y + A.z * z1v.z + A.w * z1v.w;
                mB1 += Bm.x * u1v.x + Bm.y * u1v.y + Bm.z * u1v.z + Bm.w * u1v.w;
            }
            S.P1[q][0][h] = mA0 + mB0;  S.P1[q][1][h] = mA1 + mB1;
        }
        __syncthreads();                                   // #4

        if (act) {
            float s2 = S.P1[0][s][h] + S.P1[1][s][h] + S.P1[2][s][h] + S.P1[3][s][h] + c1r;
            float sg2 = 1.f / (1.f + __expf(-s2));
            S.v2[s][h] = vw2 * sg2;
        }
        __syncthreads();                                   // #5

        // C: tv partial (W1p cols) + gA partial (Wy1 cols) fused
        {
            float tA0 = 0.f, tA1 = 0.f, gA0 = 0.f, gA1 = 0.f;
#pragma unroll
            for (int c = 0; c < 8; c++) {
                int kp = k0 + 4 * c;
                float4 a = *(const float4*)&S.v2[0][kp];
                float4 b = *(const float4*)&S.v2[1][kp];
#define STC(r, av, bv) { \
                float wA = S.W1p[(kp + r) * STRIDE + h]; \
                float wB = S.Wy1[(kp + r) * STRIDE + h]; \
                tA0 += (av) * wA;  tA1 += (bv) * wA; \
                gA0 += (av) * wB;  gA1 += (bv) * wB; }
                STC(0, a.x, b.x) STC(1, a.y, b.y) STC(2, a.z, b.z) STC(3, a.w, b.w)
#undef STC
            }
            S.P1[q][0][h] = tA0;  S.P1[q][1][h] = tA1;
            S.P2[q][0][h] = gA0;  S.P2[q][1][h] = gA1;
        }
        __syncthreads();                                   // #6

        if (act) {
            float tv = S.P1[0][s][h] + S.P1[1][s][h] + S.P1[2][s][h] + S.P1[3][s][h];
            gAr      = S.P2[0][s][h] + S.P2[1][s][h] + S.P2[2][s][h] + S.P2[3][s][h];
            S.v1[s][h] = tv * zs1r;
        }
        __syncthreads();                                   // #7

        // D: gB partial (Wy0 cols)
        {
            float g0 = 0.f, g1 = 0.f;
#pragma unroll
            for (int c = 0; c < 8; c++) {
                int kp = k0 + 4 * c;
                float4 a = *(const float4*)&S.v1[0][kp];
                float4 b = *(const float4*)&S.v1[1][kp];
#define STD(r, av, bv) { \
                float w = S.Wy0[(kp + r) * STRIDE + h]; \
                g0 += (av) * w;  g1 += (bv) * w; }
                STD(0, a.x, b.x) STD(1, a.y, b.y) STD(2, a.z, b.z) STD(3, a.w, b.w)
#undef STD
            }
            S.P1[q][0][h] = g0;  S.P1[q][1][h] = g1;
        }
        __syncthreads();                                   // #8

        float rres = 0.f;
        if (act) {
            float gB = S.P1[0][s][h] + S.P1[1][s][h] + S.P1[2][s][h] + S.P1[3][s][h];
            float g = a1r * gAr + a0r * gB + a2w + 0.5f * y1r;
            rres = yr - g;
            float qq = rres * rres;
#pragma unroll
            for (int o = 16; o; o >>= 1)
                qq += __shfl_xor_sync(0xffffffffu, qq, o);
            if ((h & 31) == 0) S.red[tid >> 5] = qq;   // warps 0..7
        }

        // flag = conv(it-2); break BEFORE this iteration's update.
        if (S.flag) { broke = 1; break; }

        if (act) {
            yhist = y1r;                       // y1_after(it-1)
            y1r += (4.f / (float)(it + 1)) * rres;
            S.yv0[s][h] = y1r * a0r;
            S.yv1[s][h] = y1r * a1r;
        }
        __syncthreads();     // #E: red/yv ready; flag not yet overwritten
    }
    if (broke && act) y1r = yhist;   // exact revert to y1_after(break_it - 2)

    // ---- output: mean over dims of (y1 + y) per sample ----
    float o = act ? (y1r + yr) : 0.f;
    if (act) {
#pragma unroll
        for (int off = 16; off; off >>= 1)
            o += __shfl_xor_sync(0xffffffffu, o, off);
        if ((h & 31) == 0) S.red[tid >> 5] = o;
    }
    __syncthreads();
    if (tid == 0) {
        out[samp]     = (S.red[0] + S.red[1] + S.red[2] + S.red[3]) * (1.f / 128.f);
        out[samp + 1] = (S.red[4] + S.red[5] + S.red[6] + S.red[7]) * (1.f / 128.f);
    }
}

extern "C" void kernel_launch(void* const* d_in, const int* in_sizes, int n_in,
                              void* d_out, int out_size) {
    (void)in_sizes; (void)n_in; (void)out_size;
    const float* x      = (const float*)d_in[0];
    const float* y      = (const float*)d_in[1];
    const float* wuu0_w = (const float*)d_in[2];
    const float* wuu0_b = (const float*)d_in[3];
    const float* wyu0_w = (const float*)d_in[4];
    const float* wyu0_b = (const float*)d_in[5];
    const float* wy0    = (const float*)d_in[6];
    const float* wu0_w  = (const float*)d_in[7];
    const float* wu0_b  = (const float*)d_in[8];
    const float* wuu1_w = (const float*)d_in[9];
    const float* wuu1_b = (const float*)d_in[10];
    const float* wzu1_w = (const float*)d_in[11];
    const float* wzu1_b = (const float*)d_in[12];
    const float* wz1    = (const float*)d_in[13];
    const float* wyu1_w = (const float*)d_in[14];
    const float* wyu1_b = (const float*)d_in[15];
    const float* wy1    = (const float*)d_in[16];
    const float* wu1_w  = (const float*)d_in[17];
    const float* wu1_b  = (const float*)d_in[18];
    const float* wzu2_w = (const float*)d_in[19];
    const float* wzu2_b = (const float*)d_in[20];
    const float* wz2    = (const float*)d_in[21];
    const float* wyu2_w = (const float*)d_in[22];
    const float* wyu2_b = (const float*)d_in[23];
    const float* wy2    = (const float*)d_in[24];
    // d_in[25] (wu2_w), d_in[26] (wu2_b) do not affect the gradient / output.

    size_t smem = sizeof(Smem);
    cudaFuncSetAttribute(pblnn_kernel, cudaFuncAttributeMaxDynamicSharedMemorySize, (int)smem);

    pblnn_init_kernel<<<(MAXIT * NCTA + 255) / 256, 256>>>();
    pblnn_kernel<<<NCTA, NTHREADS, smem>>>(
        x, y,
        wuu0_w, wuu0_b, wyu0_w, wyu0_b, wy0, wu0_w, wu0_b,
        wuu1_w, wuu1_b, wzu1_w, wzu1_b, wz1, wyu1_w, wyu1_b, wy1, wu1_w, wu1_b,
        wzu2_w, wzu2_b, wz2, wyu2_w, wyu2_b, wy2,
        (float*)d_out);
}

// round 9
// speedup vs baseline: 1.7625x; 1.0194x over previous
#include <cuda_runtime.h>
#include <math.h>

#define H        128
#define STRIDE   132      // fp32 stride: 132 % 32 == 4 -> conflict-free row+col access
#define SP       260      // packed float2 matrix stride (260 % 32 == 4)
#define PW       (2 * H + 8)
#define NCTA     128
#define NTHREADS 512
#define MAXIT    500
#define TOLF     1e-3f

// per-(iteration, CTA) residual slots; -1 = not yet posted, >=0 = posted value.
__device__ float g_part[MAXIT * NCTA];

struct __align__(16) Smem {
    float Wy0[H * STRIDE];    // fp32 rows (M1) + scalar cols (D)
    float WP[H * SP];         // interleaved (W1p, Wy1) pairs: rows (M2) + col float2 (C)
    float yv0[2][H];
    float yv1[2][H];
    float zz [2][H];
    float v2 [2][H];
    float v1 [2][H];
    float P1[4][PW];          // packed partials: [q][2h+s]
    float P2[4][PW];
    float xbuf[2][H];
    float ubuf0[2][H];
    float ubuf1[2][H];
    float red[8];
    int   flag;
};

__global__ void pblnn_init_kernel() {
    int t = blockIdx.x * blockDim.x + threadIdx.x;
    if (t < MAXIT * NCTA) g_part[t] = -1.f;
}

__device__ __forceinline__ float softplus_f(float s) {
    float e = __expf(s);
    float z = __logf(1.f + e);
    return (s > 15.f) ? s : z;
}

__device__ __forceinline__ void spsig(float s, float& z, float& sg) {
    float e = __expf(s);
    float zz_ = __logf(1.f + e);
    float sgg = e / (1.f + e);
    if (s > 15.f) { zz_ = s; sgg = 1.f; }
    z = zz_; sg = sgg;
}

// one-time single-sample dot: smem fp32 vector . gmem fp32 row (full 128)
__device__ __forceinline__ float dot1(const float* xs, const float* __restrict__ w) {
    float a = 0.f, b = 0.f;
#pragma unroll
    for (int j = 0; j < H; j += 8) {
        float4 wv0 = __ldg((const float4*)&w[j]);
        float4 wv1 = __ldg((const float4*)&w[j + 4]);
        float4 u0 = *(const float4*)&xs[j];
        float4 u1 = *(const float4*)&xs[j + 4];
        a += wv0.x * u0.x + wv0.y * u0.y + wv0.z * u0.z + wv0.w * u0.w;
        b += wv1.x * u1.x + wv1.y * u1.y + wv1.z * u1.z + wv1.w * u1.w;
    }
    return a + b;
}

// quarter dot (32 wide) for both samples: gmem weight row segment x smem vectors
__device__ __forceinline__ void qdot2(const float* __restrict__ wseg,
                                      const float* v0, const float* v1,
                                      float& p0, float& p1) {
    float a0 = 0.f, b0 = 0.f, a1 = 0.f, b1 = 0.f;
#pragma unroll
    for (int c = 0; c < 8; c += 2) {
        float4 w  = __ldg((const float4*)&wseg[4 * c]);
        float4 w2 = __ldg((const float4*)&wseg[4 * c + 4]);
        float4 x0  = *(const float4*)&v0[4 * c];
        float4 x02 = *(const float4*)&v0[4 * c + 4];
        float4 x1  = *(const float4*)&v1[4 * c];
        float4 x12 = *(const float4*)&v1[4 * c + 4];
        a0 += w.x * x0.x + w.y * x0.y + w.z * x0.z + w.w * x0.w;
        b0 += w2.x * x02.x + w2.y * x02.y + w2.z * x02.z + w2.w * x02.w;
        a1 += w.x * x1.x + w.y * x1.y + w.z * x1.z + w.w * x1.w;
        b1 += w2.x * x12.x + w2.y * x12.y + w2.z * x12.z + w2.w * x12.w;
    }
    p0 = a0 + b0; p1 = a1 + b1;
}

__global__ __launch_bounds__(NTHREADS, 1)
void pblnn_kernel(
    const float* __restrict__ x,      const float* __restrict__ y,
    const float* __restrict__ wuu0_w, const float* __restrict__ wuu0_b,
    const float* __restrict__ wyu0_w, const float* __restrict__ wyu0_b,
    const float* __restrict__ wy0,
    const float* __restrict__ wu0_w,  const float* __restrict__ wu0_b,
    const float* __restrict__ wuu1_w, const float* __restrict__ wuu1_b,
    const float* __restrict__ wzu1_w, const float* __restrict__ wzu1_b,
    const float* __restrict__ wz1,
    const float* __restrict__ wyu1_w, const float* __restrict__ wyu1_b,
    const float* __restrict__ wy1,
    const float* __restrict__ wu1_w,  const float* __restrict__ wu1_b,
    const float* __restrict__ wzu2_w, const float* __restrict__ wzu2_b,
    const float* __restrict__ wz2,
    const float* __restrict__ wyu2_w, const float* __restrict__ wyu2_b,
    const float* __restrict__ wy2,
    float* __restrict__ out)
{
    extern __shared__ char smem_raw[];
    Smem& S = *reinterpret_cast<Smem*>(smem_raw);

    const int tid  = threadIdx.x;
    const int lane = tid & 31;
    const int wrp  = tid >> 5;
    const int h    = tid & (H - 1);
    const int q    = tid >> 7;          // quarter 0..3
    const int k0   = q * 32;
    const bool act = (q < 2);           // elementwise lanes; s = q
    const int s    = q & 1;
    const int samp = blockIdx.x * 2;

    // ---- stage weights into smem + x ----
    for (int e = tid; e < H * H / 4; e += NTHREADS) {
        int r = e >> 5, c4 = (e & 31) * 4;
        *(float4*)&S.Wy0[r * STRIDE + c4] = __ldg((const float4*)&wy0[r * H + c4]);
        float4 w1 = __ldg((const float4*)&wz1[r * H + c4]);
        w1.x = fmaxf(w1.x, 0.f); w1.y = fmaxf(w1.y, 0.f);
        w1.z = fmaxf(w1.z, 0.f); w1.w = fmaxf(w1.w, 0.f);
        float4 wy = __ldg((const float4*)&wy1[r * H + c4]);
        float4 lo = make_float4(w1.x, wy.x, w1.y, wy.y);
        float4 hi = make_float4(w1.z, wy.z, w1.w, wy.w);
        *(float4*)&S.WP[r * SP + 2 * c4]     = lo;
        *(float4*)&S.WP[r * SP + 2 * c4 + 4] = hi;
    }
    for (int e = tid; e < 2 * H; e += NTHREADS)
        S.xbuf[e >> 7][e & 127] = x[samp * H + e];
    __syncthreads();

    // ---- y-independent precompute, parallelized via quarter dots ----
    float a0r = 0.f, a1r = 0.f, c0r = 0.f, c1r = 0.f, zur = 0.f;
    float vw2 = 0.f, a2w = 0.f, yr = 0.f;
    float y1r = 1.f, yhist = 1.f;
    float zs1r = 0.f, gAr = 0.f;

    // R1: wuu0 @ x -> u0 ; wyu0 @ x -> a0
    {
        float p0, p1, r0, r1;
        qdot2(&wuu0_w[h * H + k0], &S.xbuf[0][k0], &S.xbuf[1][k0], p0, p1);
        qdot2(&wyu0_w[h * H + k0], &S.xbuf[0][k0], &S.xbuf[1][k0], r0, r1);
        *(float2*)&S.P1[q][2 * h] = make_float2(p0, p1);
        *(float2*)&S.P2[q][2 * h] = make_float2(r0, r1);
    }
    __syncthreads();
    if (act) {
        int ix = 2 * h + s;
        float su = S.P1[0][ix] + S.P1[1][ix] + S.P1[2][ix] + S.P1[3][ix];
        S.ubuf0[s][h] = softplus_f(su + wuu0_b[h]);
        a0r = S.P2[0][ix] + S.P2[1][ix] + S.P2[2][ix] + S.P2[3][ix] + wyu0_b[h];
    }
    __syncthreads();
    // R2: wu0 @ x -> c0 ; wuu1 @ u0 -> u1
    {
        float p0, p1, r0, r1;
        qdot2(&wu0_w[h * H + k0], &S.xbuf[0][k0], &S.xbuf[1][k0], p0, p1);
        qdot2(&wuu1_w[h * H + k0], &S.ubuf0[0][k0], &S.ubuf0[1][k0], r0, r1);
        *(float2*)&S.P1[q][2 * h] = make_float2(p0, p1);
        *(float2*)&S.P2[q][2 * h] = make_float2(r0, r1);
    }
    __syncthreads();
    if (act) {
        int ix = 2 * h + s;
        c0r = S.P1[0][ix] + S.P1[1][ix] + S.P1[2][ix] + S.P1[3][ix] + wu0_b[h];
        float su = S.P2[0][ix] + S.P2[1][ix] + S.P2[2][ix] + S.P2[3][ix];
        S.ubuf1[s][h] = softplus_f(su + wuu1_b[h]);
    }
    __syncthreads();
    // R3: wzu1 @ u0 -> zu ; wyu1 @ u0 -> a1
    {
        float p0, p1, r0, r1;
        qdot2(&wzu1_w[h * H + k0], &S.ubuf0[0][k0], &S.ubuf0[1][k0], p0, p1);
        qdot2(&wyu1_w[h * H + k0], &S.ubuf0[0][k0], &S.ubuf0[1][k0], r0, r1);
        *(float2*)&S.P1[q][2 * h] = make_float2(p0, p1);
        *(float2*)&S.P2[q][2 * h] = make_float2(r0, r1);
    }
    __syncthreads();
    if (act) {
        int ix = 2 * h + s;
        float su = S.P1[0][ix] + S.P1[1][ix] + S.P1[2][ix] + S.P1[3][ix];
        zur = softplus_f(su + wzu1_b[h]);
        a1r = S.P2[0][ix] + S.P2[1][ix] + S.P2[2][ix] + S.P2[3][ix] + wyu1_b[h];
    }
    __syncthreads();
    // R4: wu1 @ u0 -> c1 ; wyu2 @ u1 -> a2
    {
        float p0, p1, r0, r1;
        qdot2(&wu1_w[h * H + k0], &S.ubuf0[0][k0], &S.ubuf0[1][k0], p0, p1);
        qdot2(&wyu2_w[h * H + k0], &S.ubuf1[0][k0], &S.ubuf1[1][k0], r0, r1);
        *(float2*)&S.P1[q][2 * h] = make_float2(p0, p1);
        *(float2*)&S.P2[q][2 * h] = make_float2(r0, r1);
    }
    __syncthreads();
    if (act) {
        int ix = 2 * h + s;
        c1r = S.P1[0][ix] + S.P1[1][ix] + S.P1[2][ix] + S.P1[3][ix] + wu1_b[h];
        float su = S.P2[0][ix] + S.P2[1][ix] + S.P2[2][ix] + S.P2[3][ix];
        a2w = (su + wyu2_b[h]) * wy2[h];
        // R5: single-row zu2 = sp(wzu2 . u1 + b)
        float zu2 = softplus_f(dot1(S.ubuf1[s], wzu2_w) + wzu2_b[0]);
        vw2 = zu2 * fmaxf(wz2[h], 0.f);
        yr = y[(samp + s) * H + h];
        S.yv0[s][h] = a0r;      // y1 = 1
        S.yv1[s][h] = a1r;
    }
    __syncthreads();            // yv ready for iter 0

    // ---- fixed-point iterations: lag-2, atomic-free convergence pipeline ----
    int broke = 0;
    for (int it = 0; it < MAXIT; ++it) {
        // post residual of it-1: one plain volatile store, value doubles as flag
        if (tid == 416 && it > 0) {
            float n0 = sqrtf(S.red[0] + S.red[1] + S.red[2] + S.red[3]);
            float n1 = sqrtf(S.red[4] + S.red[5] + S.red[6] + S.red[7]);
            *((volatile float*)&g_part[(it - 1) * NCTA + blockIdx.x]) = n0 + n1;
        }
        // checker warp: cooperative poll + sum of lag-2 slots (overlaps M1)
        if (wrp == 12) {
            int f = 0;
            if (it >= 2) {
                volatile const float* gp = &g_part[(it - 2) * NCTA];
                float sum;
                for (;;) {
                    float v0 = gp[lane], v1 = gp[lane + 32];
                    float v2 = gp[lane + 64], v3 = gp[lane + 96];
                    bool ok = (v0 >= 0.f) & (v1 >= 0.f) & (v2 >= 0.f) & (v3 >= 0.f);
                    if (__all_sync(0xffffffffu, ok)) { sum = v0 + v1 + v2 + v3; break; }
                }
#pragma unroll
                for (int o = 16; o; o >>= 1)
                    sum += __shfl_xor_sync(0xffffffffu, sum, o);
                if (sum * (1.f / 256.f) < TOLF) f = 1;
            }
            if (lane == 0) S.flag = f;
        }

        // M1: s1 partial = Wy0[h][k0..k0+32) . yv0
        {
            const float4* W  = (const float4*)&S.Wy0[h * STRIDE + k0];
            const float4* V0 = (const float4*)&S.yv0[0][k0];
            const float4* V1 = (const float4*)&S.yv0[1][k0];
            float m0a = 0.f, m0b = 0.f, m1a = 0.f, m1b = 0.f;
#pragma unroll
            for (int c = 0; c < 8; c += 2) {
                float4 w = W[c], a = V0[c], b = V1[c];
                m0a += w.x * a.x + w.y * a.y + w.z * a.z + w.w * a.w;
                m1a += w.x * b.x + w.y * b.y + w.z * b.z + w.w * b.w;
                float4 w2 = W[c + 1], a2 = V0[c + 1], b2 = V1[c + 1];
                m0b += w2.x * a2.x + w2.y * a2.y + w2.z * a2.z + w2.w * a2.w;
                m1b += w2.x * b2.x + w2.y * b2.y + w2.z * b2.z + w2.w * b2.w;
            }
            *(float2*)&S.P1[q][2 * h] = make_float2(m0a + m0b, m1a + m1b);
        }
        __syncthreads();                                   // #2

        // flag = conv(it-2), stable after #2; break BEFORE this iteration's update.
        // y1 currently = y1_after(it-1); required = y1_after(it-2) = yhist.
        if (S.flag) { broke = 1; break; }

        if (act) {
            int ix = 2 * h + s;
            float s1 = S.P1[0][ix] + S.P1[1][ix] + S.P1[2][ix] + S.P1[3][ix] + c0r;
            float z1, sg1;
            spsig(s1, z1, sg1);
            zs1r = sg1 * zur;
            S.zz[s][h] = z1 * zur;
        }
        __syncthreads();                                   // #3

        // M2: s2 partial = W1p@zz + Wy1@yv1 via packed WP rows
        {
            const float4* WA = (const float4*)&S.WP[h * SP + 2 * k0];
            const float4* Z0 = (const float4*)&S.zz[0][k0];
            const float4* Z1 = (const float4*)&S.zz[1][k0];
            const float4* Y0 = (const float4*)&S.yv1[0][k0];
            const float4* Y1 = (const float4*)&S.yv1[1][k0];
            float mA0 = 0.f, mA1 = 0.f, mB0 = 0.f, mB1 = 0.f;
#pragma unroll
            for (int c = 0; c < 8; c++) {
                float4 wlo = WA[2 * c];       // (w1p_k, wy1_k, w1p_k1, wy1_k1)
                float4 whi = WA[2 * c + 1];   // (w1p_k2, wy1_k2, w1p_k3, wy1_k3)
                float4 z0 = Z0[c], z1v = Z1[c], u0v = Y0[c], u1v = Y1[c];
                mA0 += wlo.x * z0.x + wlo.z * z0.y + whi.x * z0.z + whi.z * z0.w;
                mB0 += wlo.y * u0v.x + wlo.w * u0v.y + whi.y * u0v.z + whi.w * u0v.w;
                mA1 += wlo.x * z1v.x + wlo.z * z1v.y + whi.x * z1v.z + whi.z * z1v.w;
                mB1 += wlo.y * u1v.x + wlo.w * u1v.y + whi.y * u1v.z + whi.w * u1v.w;
            }
            *(float2*)&S.P1[q][2 * h] = make_float2(mA0 + mB0, mA1 + mB1);
        }
        __syncthreads();                                   // #4

        if (act) {
            int ix = 2 * h + s;
            float s2 = S.P1[0][ix] + S.P1[1][ix] + S.P1[2][ix] + S.P1[3][ix] + c1r;
            float sg2 = 1.f / (1.f + __expf(-s2));
            S.v2[s][h] = vw2 * sg2;
        }
        __syncthreads();                                   // #5

        // C: tv partial (W1p cols) + gA partial (Wy1 cols) via packed WP col float2
        {
            float tA0 = 0.f, tA1 = 0.f, gA0 = 0.f, gA1 = 0.f;
#pragma unroll
            for (int c = 0; c < 8; c++) {
                int kp = k0 + 4 * c;
                float4 a = *(const float4*)&S.v2[0][kp];
                float4 b = *(const float4*)&S.v2[1][kp];
#define STC(r, av, bv) { \
                float2 wc = *(const float2*)&S.WP[(kp + r) * SP + 2 * h]; \
                tA0 += (av) * wc.x;  tA1 += (bv) * wc.x; \
                gA0 += (av) * wc.y;  gA1 += (bv) * wc.y; }
                STC(0, a.x, b.x) STC(1, a.y, b.y) STC(2, a.z, b.z) STC(3, a.w, b.w)
#undef STC
            }
            *(float2*)&S.P1[q][2 * h] = make_float2(tA0, tA1);
            *(float2*)&S.P2[q][2 * h] = make_float2(gA0, gA1);
        }
        __syncthreads();                                   // #6

        if (act) {
            int ix = 2 * h + s;
            float tv = S.P1[0][ix] + S.P1[1][ix] + S.P1[2][ix] + S.P1[3][ix];
            gAr      = S.P2[0][ix] + S.P2[1][ix] + S.P2[2][ix] + S.P2[3][ix];
            S.v1[s][h] = tv * zs1r;
        }
        __syncthreads();                                   // #7

        // D: gB partial (Wy0 cols, scalar)
        {
            float g0 = 0.f, g1 = 0.f;
#pragma unroll
            for (int c = 0; c < 8; c++) {
                int kp = k0 + 4 * c;
                float4 a = *(const float4*)&S.v1[0][kp];
                float4 b = *(const float4*)&S.v1[1][kp];
#define STD(r, av, bv) { \
                float w = S.Wy0[(kp + r) * STRIDE + h]; \
                g0 += (av) * w;  g1 += (bv) * w; }
                STD(0, a.x, b.x) STD(1, a.y, b.y) STD(2, a.z, b.z) STD(3, a.w, b.w)
#undef STD
            }
            *(float2*)&S.P1[q][2 * h] = make_float2(g0, g1);
        }
        __syncthreads();                                   // #8

        float rres = 0.f;
        if (act) {
            int ix = 2 * h + s;
            float gB = S.P1[0][ix] + S.P1[1][ix] + S.P1[2][ix] + S.P1[3][ix];
            float g = a1r * gAr + a0r * gB + a2w + 0.5f * y1r;
            rres = yr - g;
            float qq = rres * rres;
#pragma unroll
            for (int o = 16; o; o >>= 1)
                qq += __shfl_xor_sync(0xffffffffu, qq, o);
            if ((h & 31) == 0) S.red[tid >> 5] = qq;   // warps 0..7
        }

        if (act) {
            yhist = y1r;                       // y1_after(it-1)
            y1r += (4.f / (float)(it + 1)) * rres;
            S.yv0[s][h] = y1r * a0r;
            S.yv1[s][h] = y1r * a1r;
        }
        __syncthreads();     // #E: red/yv ready; flag not yet overwritten
    }
    if (broke && act) y1r = yhist;   // exact revert to y1_after(break_it - 2)

    // ---- output: mean over dims of (y1 + y) per sample ----
    float o = act ? (y1r + yr) : 0.f;
    if (act) {
#pragma unroll
        for (int off = 16; off; off >>= 1)
            o += __shfl_xor_sync(0xffffffffu, o, off);
        if ((h & 31) == 0) S.red[tid >> 5] = o;
    }
    __syncthreads();
    if (tid == 0) {
        out[samp]     = (S.red[0] + S.red[1] + S.red[2] + S.red[3]) * (1.f / 128.f);
        out[samp + 1] = (S.red[4] + S.red[5] + S.red[6] + S.red[7]) * (1.f / 128.f);
    }
}

extern "C" void kernel_launch(void* const* d_in, const int* in_sizes, int n_in,
                              void* d_out, int out_size) {
    (void)in_sizes; (void)n_in; (void)out_size;
    const float* x      = (const float*)d_in[0];
    const float* y      = (const float*)d_in[1];
    const float* wuu0_w = (const float*)d_in[2];
    const float* wuu0_b = (const float*)d_in[3];
    const float* wyu0_w = (const float*)d_in[4];
    const float* wyu0_b = (const float*)d_in[5];
    const float* wy0    = (const float*)d_in[6];
    const float* wu0_w  = (const float*)d_in[7];
    const float* wu0_b  = (const float*)d_in[8];
    const float* wuu1_w = (const float*)d_in[9];
    const float* wuu1_b = (const float*)d_in[10];
    const float* wzu1_w = (const float*)d_in[11];
    const float* wzu1_b = (const float*)d_in[12];
    const float* wz1    = (const float*)d_in[13];
    const float* wyu1_w = (const float*)d_in[14];
    const float* wyu1_b = (const float*)d_in[15];
    const float* wy1    = (const float*)d_in[16];
    const float* wu1_w  = (const float*)d_in[17];
    const float* wu1_b  = (const float*)d_in[18];
    const float* wzu2_w = (const float*)d_in[19];
    const float* wzu2_b = (const float*)d_in[20];
    const float* wz2    = (const float*)d_in[21];
    const float* wyu2_w = (const float*)d_in[22];
    const float* wyu2_b = (const float*)d_in[23];
    const float* wy2    = (const float*)d_in[24];
    // d_in[25] (wu2_w), d_in[26] (wu2_b) do not affect the gradient / output.

    size_t smem = sizeof(Smem);
    cudaFuncSetAttribute(pblnn_kernel, cudaFuncAttributeMaxDynamicSharedMemorySize, (int)smem);

    pblnn_init_kernel<<<(MAXIT * NCTA + 255) / 256, 256>>>();
    pblnn_kernel<<<NCTA, NTHREADS, smem>>>(
        x, y,
        wuu0_w, wuu0_b, wyu0_w, wyu0_b, wy0, wu0_w, wu0_b,
        wuu1_w, wuu1_b, wzu1_w, wzu1_b, wz1, wyu1_w, wyu1_b, wy1, wu1_w, wu1_b,
        wzu2_w, wzu2_b, wz2, wyu2_w, wyu2_b, wy2,
        (float*)d_out);
}